// round 4
// baseline (speedup 1.0000x reference)
#include <cuda_runtime.h>
#include <cuda_bf16.h>
#include <math.h>

#define LSEQ 512
#define DIM 768
#define DFF 3072
#define NLAYERS 8
#define NE 8
#define NSTEPS 2
#define VOCAB 50257
#define RHID 384
#define KSZ 4

// ---------------- device scratch (no cudaMalloc allowed) ----------------
__device__ double g_abssum[40];
__device__ float  g_scal[4];
__device__ float  g_x[LSEQ * DIM];
__device__ float  g_h[LSEQ * DIM];
__device__ float  g_proj[LSEQ * 2 * DIM];
__device__ float  g_mix[LSEQ * DIM];
__device__ float  g_rh[LSEQ * RHID];
__device__ float  g_cx[LSEQ];
__device__ float  g_hard[LSEQ];
__device__ float  g_cur[LSEQ * DIM];
__device__ float  g_ctxb[LSEQ * DIM];
__device__ float  g_glog[LSEQ * NE];
__device__ int    g_cnt[NE];
__device__ int    g_tokslot[NE * LSEQ];
__device__ float  g_hmid[LSEQ * DFF];
__device__ float  g_eo[2 * LSEQ * DIM];
__device__ float  g_selin[LSEQ * DIM];

// ---------------- helpers ----------------
__device__ __forceinline__ float blockReduceSum(float v) {
    __shared__ float sh[32];
    int lane = threadIdx.x & 31, wid = threadIdx.x >> 5;
#pragma unroll
    for (int o = 16; o; o >>= 1) v += __shfl_down_sync(0xffffffffu, v, o);
    if (lane == 0) sh[wid] = v;
    __syncthreads();
    int nw = (blockDim.x + 31) >> 5;
    v = (threadIdx.x < nw) ? sh[threadIdx.x] : 0.f;
    if (wid == 0) {
#pragma unroll
        for (int o = 16; o; o >>= 1) v += __shfl_down_sync(0xffffffffu, v, o);
    }
    return v;  // valid on thread 0
}

// ---------------- small kernels ----------------
__global__ void zero_kernel(double* abss, float* scal) {
    int t = threadIdx.x;
    if (t < 40) abss[t] = 0.0;
    if (t < 4) scal[t] = 0.f;
}

__global__ void absmean_kernel(const float* __restrict__ w, long per, double* __restrict__ acc) {
    const float* p = w + (long)blockIdx.y * per;
    float s = 0.f;
    long stride = (long)gridDim.x * blockDim.x;
    for (long i = (long)blockIdx.x * blockDim.x + threadIdx.x; i < per; i += stride)
        s += fabsf(p[i]);
    s = blockReduceSum(s);
    if (threadIdx.x == 0) atomicAdd(acc + blockIdx.y, (double)s);
}

__global__ void embed_kernel(const int* __restrict__ ids, const float* __restrict__ emb,
                             float* __restrict__ x) {
    int l = blockIdx.x;
    long row = ids[l];
    const float4* src = reinterpret_cast<const float4*>(emb + row * DIM);
    float4* dst = reinterpret_cast<float4*>(x + (long)l * DIM);
    for (int i = threadIdx.x; i < DIM / 4; i += blockDim.x) dst[i] = src[i];
}

__global__ void rmsnorm_kernel(const float* __restrict__ x, const float* __restrict__ w,
                               float* __restrict__ out) {
    int l = blockIdx.x;
    const float* xr = x + (long)l * DIM;
    float v0 = xr[threadIdx.x], v1 = xr[threadIdx.x + 256], v2 = xr[threadIdx.x + 512];
    float s = blockReduceSum(v0 * v0 + v1 * v1 + v2 * v2);
    __shared__ float rstd;
    if (threadIdx.x == 0) rstd = rsqrtf(s / (float)DIM + 1e-6f);
    __syncthreads();
    float r = rstd;
    float* o = out + (long)l * DIM;
    o[threadIdx.x]       = w[threadIdx.x]       * v0 * r;
    o[threadIdx.x + 256] = w[threadIdx.x + 256] * v1 * r;
    o[threadIdx.x + 512] = w[threadIdx.x + 512] * v2 * r;
}

__global__ void convmix_kernel(const float* __restrict__ proj, const float* __restrict__ cw,
                               const float* __restrict__ cb, float* __restrict__ mix) {
    int l = blockIdx.x, d = threadIdx.x;
    float acc = cb[d];
#pragma unroll
    for (int k = 0; k < KSZ; k++) {
        int src = l - (KSZ - 1) + k;
        if (src >= 0) acc += proj[(long)src * (2 * DIM) + d] * cw[d * KSZ + k];
    }
    float gz = proj[(long)l * (2 * DIM) + DIM + d];
    float gate = gz / (1.f + expf(-gz));
    mix[(long)l * DIM + d] = acc * gate;
}

__global__ void cxpost_kernel(const float* __restrict__ cx, float* __restrict__ hard,
                              float* __restrict__ scal) {
    int t = threadIdx.x;  // 512
    float v = cx[t];
    hard[t] = (v > 0.5f) ? 1.f : 0.f;
    float s = blockReduceSum(v);
    if (t == 0) scal[0] = (s * (1.f / (float)LSEQ) > 0.1f) ? 1.f : 0.f;
}

__global__ void ctx_kernel(const float* __restrict__ cur, const float* __restrict__ te,
                           float* __restrict__ ctx, int* __restrict__ cnt) {
    int l = blockIdx.x, d = threadIdx.x;
    ctx[(long)l * DIM + d] = cur[(long)l * DIM + d] + te[d];
    if (l == 0 && d < NE) cnt[d] = 0;
}

__global__ void route_kernel(const float* __restrict__ glog, int* __restrict__ cnt,
                             int* __restrict__ tokslot) {
    int t = blockIdx.x * blockDim.x + threadIdx.x;
    if (t >= LSEQ) return;
    const float* p = glog + (long)t * NE;
    int s0 = 0; float b0 = p[0];
#pragma unroll
    for (int e = 1; e < NE; e++) { float v = p[e]; if (v > b0) { b0 = v; s0 = e; } }
    int s1 = -1; float b1 = -1e30f;
#pragma unroll
    for (int e = 0; e < NE; e++) {
        if (e == s0) continue;
        float v = p[e]; if (v > b1) { b1 = v; s1 = e; }
    }
    int p0 = atomicAdd(&cnt[s0], 1);
    tokslot[s0 * LSEQ + p0] = t;              // slot 0
    int p1 = atomicAdd(&cnt[s1], 1);
    tokslot[s1 * LSEQ + p1] = t | (1 << 16);  // slot 1
}

// refined = rmsnorm(eo0+eo1+cur, cnw); cur = hard ? refined : cur
__global__ void combine_kernel(const float* __restrict__ eo, float* __restrict__ cur,
                               const float* __restrict__ cnw, const float* __restrict__ hard) {
    int l = blockIdx.x;
    float hsel = hard[l];
    float vv[3]; float local = 0.f;
#pragma unroll
    for (int c = 0; c < 3; c++) {
        int d = threadIdx.x + c * 256;
        float v = eo[(long)l * DIM + d] + eo[(long)(LSEQ + l) * DIM + d] + cur[(long)l * DIM + d];
        vv[c] = v; local += v * v;
    }
    float s = blockReduceSum(local);
    __shared__ float rstd;
    if (threadIdx.x == 0) rstd = rsqrtf(s / (float)DIM + 1e-6f);
    __syncthreads();
    float r = rstd;
#pragma unroll
    for (int c = 0; c < 3; c++) {
        int d = threadIdx.x + c * 256;
        float refined = cnw[d] * vv[c] * r;
        float old = cur[(long)l * DIM + d];
        cur[(long)l * DIM + d] = refined * hsel + old * (1.f - hsel);
    }
}

__global__ void select_kernel(const float* __restrict__ core, const float* __restrict__ cur,
                              const float* __restrict__ scal, float* __restrict__ outp) {
    int i = blockIdx.x * blockDim.x + threadIdx.x;
    if (i < LSEQ * DIM) outp[i] = (scal[0] > 0.5f) ? cur[i] : core[i];
}

// ---------------- quantized GEMM (64x64x16, double-buffered) ----------------
// C[M,N] = act( g * (A[M,K] @ ternary(W[N,K])^T) ) (+R)
// ACT: 0 none, 1 relu, 2 gelu(exact), 3 sigmoid
// AGATH: A rows gathered via tokSlot (token id in low 16 bits), M = *cntPtr
// CSCAT: C rows scattered to g_eo[(slot*LSEQ+tok)*DIM + col], M = *cntPtr
template <int ACT, bool RESID, bool AGATH, bool CSCAT>
__global__ __launch_bounds__(256) void gemm_q(
    const float* __restrict__ A, int lda,
    const float* __restrict__ W,
    const double* __restrict__ abssum, float invNw,
    float* __restrict__ C, int ldc,
    int M, int N, int K,
    const float* __restrict__ R,
    const int* __restrict__ tokSlot,
    const int* __restrict__ cntPtr) {
    if (AGATH || CSCAT) M = *cntPtr;
    int bm = blockIdx.y * 64;
    if (bm >= M) return;
    int bn = blockIdx.x * 64;

    float g = fmaxf((float)(*abssum) * invNw, 1e-5f);
    float inv_g = 1.f / g;

    __shared__ float As[2][16][64];
    __shared__ float Ws[2][16][64];

    int tid = threadIdx.x;
    int tx = tid & 15;   // n micro
    int ty = tid >> 4;   // m micro
    float acc[4][4] = {};

    int lm = tid >> 2;
    int lk = (tid & 3) * 4;
    int arow = bm + lm;
    bool arow_ok = arow < M;
    long aoff;
    if (AGATH) {
        int tok = arow_ok ? (tokSlot[arow] & 0xFFFF) : 0;
        aoff = (long)tok * lda;
    } else {
        aoff = (long)arow * lda;
    }
    int wrow = bn + lm;
    bool wrow_ok = wrow < N;
    long woff = (long)wrow * K;

    // prologue: chunk 0 -> buffer 0
    float4 av = make_float4(0.f, 0.f, 0.f, 0.f);
    float4 wv = make_float4(0.f, 0.f, 0.f, 0.f);
    if (arow_ok) av = *reinterpret_cast<const float4*>(A + aoff + lk);
    if (wrow_ok) wv = *reinterpret_cast<const float4*>(W + woff + lk);
    wv.x = fminf(fmaxf(rintf(wv.x * inv_g), -1.f), 1.f);
    wv.y = fminf(fmaxf(rintf(wv.y * inv_g), -1.f), 1.f);
    wv.z = fminf(fmaxf(rintf(wv.z * inv_g), -1.f), 1.f);
    wv.w = fminf(fmaxf(rintf(wv.w * inv_g), -1.f), 1.f);
    As[0][lk + 0][lm] = av.x; As[0][lk + 1][lm] = av.y;
    As[0][lk + 2][lm] = av.z; As[0][lk + 3][lm] = av.w;
    Ws[0][lk + 0][lm] = wv.x; Ws[0][lk + 1][lm] = wv.y;
    Ws[0][lk + 2][lm] = wv.z; Ws[0][lk + 3][lm] = wv.w;
    __syncthreads();

    int buf = 0;
    for (int k0 = 0; k0 < K; k0 += 16) {
        int kn = k0 + 16;
        bool more = kn < K;
        if (more) {
            av = make_float4(0.f, 0.f, 0.f, 0.f);
            wv = make_float4(0.f, 0.f, 0.f, 0.f);
            if (arow_ok) av = *reinterpret_cast<const float4*>(A + aoff + kn + lk);
            if (wrow_ok) wv = *reinterpret_cast<const float4*>(W + woff + kn + lk);
            wv.x = fminf(fmaxf(rintf(wv.x * inv_g), -1.f), 1.f);
            wv.y = fminf(fmaxf(rintf(wv.y * inv_g), -1.f), 1.f);
            wv.z = fminf(fmaxf(rintf(wv.z * inv_g), -1.f), 1.f);
            wv.w = fminf(fmaxf(rintf(wv.w * inv_g), -1.f), 1.f);
        }
#pragma unroll
        for (int kk = 0; kk < 16; kk++) {
            float4 a4 = *reinterpret_cast<const float4*>(&As[buf][kk][ty * 4]);
            float4 b4 = *reinterpret_cast<const float4*>(&Ws[buf][kk][tx * 4]);
            float avv[4] = {a4.x, a4.y, a4.z, a4.w};
            float bvv[4] = {b4.x, b4.y, b4.z, b4.w};
#pragma unroll
            for (int i = 0; i < 4; i++)
#pragma unroll
                for (int j = 0; j < 4; j++) acc[i][j] += avv[i] * bvv[j];
        }
        if (more) {
            int nb = buf ^ 1;
            As[nb][lk + 0][lm] = av.x; As[nb][lk + 1][lm] = av.y;
            As[nb][lk + 2][lm] = av.z; As[nb][lk + 3][lm] = av.w;
            Ws[nb][lk + 0][lm] = wv.x; Ws[nb][lk + 1][lm] = wv.y;
            Ws[nb][lk + 2][lm] = wv.z; Ws[nb][lk + 3][lm] = wv.w;
            __syncthreads();
            buf = nb;
        }
    }

#pragma unroll
    for (int i = 0; i < 4; i++) {
        int row = bm + ty * 4 + i;
        if (row >= M) continue;
#pragma unroll
        for (int j = 0; j < 4; j++) {
            int col = bn + tx * 4 + j;
            if (col >= N) continue;
            float v = acc[i][j] * g;
            if (ACT == 1) v = fmaxf(v, 0.f);
            else if (ACT == 2) v = 0.5f * v * (1.f + erff(v * 0.70710678118654752f));
            else if (ACT == 3) v = 1.f / (1.f + expf(-v));
            if (RESID) v += R[(long)row * ldc + col];
            if (CSCAT) {
                int ts = tokSlot[row];
                int tok = ts & 0xFFFF, slot = ts >> 16;
                C[((long)slot * LSEQ + tok) * DIM + col] = v;
            } else {
                C[(long)row * ldc + col] = v;
            }
        }
    }
}

// ---------------- big quantized GEMM (128x128x16, double-buffered) ----------------
// For the LM head: C[M,N] = g * (A @ ternary(W)^T). K must be a multiple of 16.
__global__ __launch_bounds__(256) void gemm_q_big(
    const float* __restrict__ A, int lda,
    const float* __restrict__ W,
    const double* __restrict__ abssum, float invNw,
    float* __restrict__ C, int ldc,
    int M, int N, int K) {
    int bm = blockIdx.y * 128;
    int bn = blockIdx.x * 128;
    if (bm >= M) return;

    float g = fmaxf((float)(*abssum) * invNw, 1e-5f);
    float inv_g = 1.f / g;

    __shared__ float As[2][16][132];   // 132 = 128+4 pad, keeps 16B alignment
    __shared__ float Ws[2][16][132];

    int tid = threadIdx.x;
    int lr = tid >> 1;          // 0..127 : tile row
    int lk = (tid & 1) * 8;     // 0 or 8 : k offset (each thread covers 8 k's)

    int arow = bm + lr;
    bool a_ok = arow < M;
    const float* aptr = A + (long)(a_ok ? arow : 0) * lda;
    int wrow = bn + lr;
    bool w_ok = wrow < N;
    const float* wptr = W + (long)(w_ok ? wrow : 0) * K;

    int tx = tid & 15;          // n micro (8 cols)
    int ty = tid >> 4;          // m micro (8 rows)
    float acc[8][8] = {};

#define QW4(v) do { \
    (v).x = fminf(fmaxf(rintf((v).x * inv_g), -1.f), 1.f); \
    (v).y = fminf(fmaxf(rintf((v).y * inv_g), -1.f), 1.f); \
    (v).z = fminf(fmaxf(rintf((v).z * inv_g), -1.f), 1.f); \
    (v).w = fminf(fmaxf(rintf((v).w * inv_g), -1.f), 1.f); \
} while (0)

    // prologue: chunk k0=0 -> buffer 0
    float4 av0 = make_float4(0.f, 0.f, 0.f, 0.f), av1 = av0;
    float4 wv0 = av0, wv1 = av0;
    if (a_ok) {
        av0 = *reinterpret_cast<const float4*>(aptr + lk);
        av1 = *reinterpret_cast<const float4*>(aptr + lk + 4);
    }
    if (w_ok) {
        wv0 = *reinterpret_cast<const float4*>(wptr + lk);
        wv1 = *reinterpret_cast<const float4*>(wptr + lk + 4);
    }
    QW4(wv0); QW4(wv1);
    As[0][lk + 0][lr] = av0.x; As[0][lk + 1][lr] = av0.y;
    As[0][lk + 2][lr] = av0.z; As[0][lk + 3][lr] = av0.w;
    As[0][lk + 4][lr] = av1.x; As[0][lk + 5][lr] = av1.y;
    As[0][lk + 6][lr] = av1.z; As[0][lk + 7][lr] = av1.w;
    Ws[0][lk + 0][lr] = wv0.x; Ws[0][lk + 1][lr] = wv0.y;
    Ws[0][lk + 2][lr] = wv0.z; Ws[0][lk + 3][lr] = wv0.w;
    Ws[0][lk + 4][lr] = wv1.x; Ws[0][lk + 5][lr] = wv1.y;
    Ws[0][lk + 6][lr] = wv1.z; Ws[0][lk + 7][lr] = wv1.w;
    __syncthreads();

    int buf = 0;
    for (int k0 = 0; k0 < K; k0 += 16) {
        int kn = k0 + 16;
        bool more = kn < K;
        if (more) {
            av0 = make_float4(0.f, 0.f, 0.f, 0.f); av1 = av0; wv0 = av0; wv1 = av0;
            if (a_ok) {
                av0 = *reinterpret_cast<const float4*>(aptr + kn + lk);
                av1 = *reinterpret_cast<const float4*>(aptr + kn + lk + 4);
            }
            if (w_ok) {
                wv0 = *reinterpret_cast<const float4*>(wptr + kn + lk);
                wv1 = *reinterpret_cast<const float4*>(wptr + kn + lk + 4);
            }
            QW4(wv0); QW4(wv1);
        }
#pragma unroll
        for (int kk = 0; kk < 16; kk++) {
            float4 a0 = *reinterpret_cast<const float4*>(&As[buf][kk][ty * 8]);
            float4 a1 = *reinterpret_cast<const float4*>(&As[buf][kk][ty * 8 + 4]);
            float4 b0 = *reinterpret_cast<const float4*>(&Ws[buf][kk][tx * 8]);
            float4 b1 = *reinterpret_cast<const float4*>(&Ws[buf][kk][tx * 8 + 4]);
            float af[8] = {a0.x, a0.y, a0.z, a0.w, a1.x, a1.y, a1.z, a1.w};
            float bf[8] = {b0.x, b0.y, b0.z, b0.w, b1.x, b1.y, b1.z, b1.w};
#pragma unroll
            for (int i = 0; i < 8; i++)
#pragma unroll
                for (int j = 0; j < 8; j++) acc[i][j] += af[i] * bf[j];
        }
        if (more) {
            int nb = buf ^ 1;
            As[nb][lk + 0][lr] = av0.x; As[nb][lk + 1][lr] = av0.y;
            As[nb][lk + 2][lr] = av0.z; As[nb][lk + 3][lr] = av0.w;
            As[nb][lk + 4][lr] = av1.x; As[nb][lk + 5][lr] = av1.y;
            As[nb][lk + 6][lr] = av1.z; As[nb][lk + 7][lr] = av1.w;
            Ws[nb][lk + 0][lr] = wv0.x; Ws[nb][lk + 1][lr] = wv0.y;
            Ws[nb][lk + 2][lr] = wv0.z; Ws[nb][lk + 3][lr] = wv0.w;
            Ws[nb][lk + 4][lr] = wv1.x; Ws[nb][lk + 5][lr] = wv1.y;
            Ws[nb][lk + 6][lr] = wv1.z; Ws[nb][lk + 7][lr] = wv1.w;
            __syncthreads();
            buf = nb;
        }
    }
#undef QW4

#pragma unroll
    for (int i = 0; i < 8; i++) {
        int row = bm + ty * 8 + i;
        if (row >= M) continue;
        float* crow = C + (long)row * ldc;
#pragma unroll
        for (int j = 0; j < 8; j++) {
            int col = bn + tx * 8 + j;
            if (col < N) crow[col] = acc[i][j] * g;
        }
    }
}

// ---------------- host ----------------
extern "C" void kernel_launch(void* const* d_in, const int* in_sizes, int n_in,
                              void* d_out, int out_size) {
    const int*   ids    = (const int*)d_in[0];
    const float* emb    = (const float*)d_in[1];
    const float* norm_w = (const float*)d_in[2];
    const float* in_w   = (const float*)d_in[3];
    const float* conv_w = (const float*)d_in[4];
    const float* conv_b = (const float*)d_in[5];
    const float* out_w  = (const float*)d_in[6];
    const float* rw1    = (const float*)d_in[7];
    const float* rw2    = (const float*)d_in[8];
    const float* gw     = (const float*)d_in[9];
    const float* te     = (const float*)d_in[10];
    const float* e1     = (const float*)d_in[11];
    const float* e2     = (const float*)d_in[12];
    const float* cnw    = (const float*)d_in[13];
    const float* hw     = (const float*)d_in[14];
    float* out = (float*)d_out;

    double *abss;
    float *xb, *hb, *projb, *mixb, *rhb, *cxb, *hardb, *curb, *ctxb, *glogb, *hmidb, *eob, *selb, *scal;
    int *cntb, *tsb;
    cudaGetSymbolAddress((void**)&abss,  g_abssum);
    cudaGetSymbolAddress((void**)&scal,  g_scal);
    cudaGetSymbolAddress((void**)&xb,    g_x);
    cudaGetSymbolAddress((void**)&hb,    g_h);
    cudaGetSymbolAddress((void**)&projb, g_proj);
    cudaGetSymbolAddress((void**)&mixb,  g_mix);
    cudaGetSymbolAddress((void**)&rhb,   g_rh);
    cudaGetSymbolAddress((void**)&cxb,   g_cx);
    cudaGetSymbolAddress((void**)&hardb, g_hard);
    cudaGetSymbolAddress((void**)&curb,  g_cur);
    cudaGetSymbolAddress((void**)&ctxb,  g_ctxb);
    cudaGetSymbolAddress((void**)&glogb, g_glog);
    cudaGetSymbolAddress((void**)&cntb,  g_cnt);
    cudaGetSymbolAddress((void**)&tsb,   g_tokslot);
    cudaGetSymbolAddress((void**)&hmidb, g_hmid);
    cudaGetSymbolAddress((void**)&eob,   g_eo);
    cudaGetSymbolAddress((void**)&selb,  g_selin);

    // ---- per-tensor absmean scales ----
    zero_kernel<<<1, 64>>>(abss, scal);
    absmean_kernel<<<dim3(256, NLAYERS), 256>>>(in_w,  (long)2 * DIM * DIM, abss + 0);
    absmean_kernel<<<dim3(128, NLAYERS), 256>>>(out_w, (long)DIM * DIM,     abss + 8);
    absmean_kernel<<<dim3(64, 1),  256>>>(rw1, (long)RHID * DIM, abss + 16);
    absmean_kernel<<<dim3(1, 1),   256>>>(rw2, (long)RHID,       abss + 17);
    absmean_kernel<<<dim3(4, 1),   256>>>(gw,  (long)NE * DIM,   abss + 18);
    absmean_kernel<<<dim3(256, NE), 256>>>(e1, (long)DFF * DIM,  abss + 19);
    absmean_kernel<<<dim3(256, NE), 256>>>(e2, (long)DFF * DIM,  abss + 27);
    absmean_kernel<<<dim3(512, 1), 256>>>(hw,  (long)VOCAB * DIM, abss + 35);

    // ---- embedding ----
    embed_kernel<<<LSEQ, 192>>>(ids, emb, xb);

    // ---- Mamba-style layers ----
    for (int i = 0; i < NLAYERS; i++) {
        rmsnorm_kernel<<<LSEQ, 256>>>(xb, norm_w + (long)i * DIM, hb);
        gemm_q<0, false, false, false><<<dim3(24, 8), 256>>>(
            hb, DIM, in_w + (long)i * 2 * DIM * DIM, abss + i, 1.f / (2.f * DIM * DIM),
            projb, 2 * DIM, LSEQ, 2 * DIM, DIM, nullptr, nullptr, nullptr);
        convmix_kernel<<<LSEQ, DIM>>>(projb, conv_w + (long)i * DIM * KSZ,
                                      conv_b + (long)i * DIM, mixb);
        gemm_q<0, true, false, false><<<dim3(12, 8), 256>>>(
            mixb, DIM, out_w + (long)i * DIM * DIM, abss + 8 + i, 1.f / ((float)DIM * DIM),
            xb, DIM, LSEQ, DIM, DIM, xb, nullptr, nullptr);
    }
    // xb now holds `core`

    // ---- ComplexityRouter ----
    gemm_q<1, false, false, false><<<dim3(6, 8), 256>>>(
        xb, DIM, rw1, abss + 16, 1.f / ((float)RHID * DIM),
        rhb, RHID, LSEQ, RHID, DIM, nullptr, nullptr, nullptr);
    gemm_q<3, false, false, false><<<dim3(1, 8), 256>>>(
        rhb, RHID, rw2, abss + 17, 1.f / (float)RHID,
        cxb, 1, LSEQ, 1, RHID, nullptr, nullptr, nullptr);
    cxpost_kernel<<<1, 512>>>(cxb, hardb, scal);

    // ---- DiffusionCouncil ----
    cudaMemcpyAsync(curb, xb, (size_t)LSEQ * DIM * sizeof(float), cudaMemcpyDeviceToDevice);
    for (int t = 0; t < NSTEPS; t++) {
        ctx_kernel<<<LSEQ, DIM>>>(curb, te + (long)t * DIM, ctxb, cntb);
        gemm_q<0, false, false, false><<<dim3(1, 8), 256>>>(
            ctxb, DIM, gw, abss + 18, 1.f / ((float)NE * DIM),
            glogb, NE, LSEQ, NE, DIM, nullptr, nullptr, nullptr);
        route_kernel<<<2, 256>>>(glogb, cntb, tsb);
        for (int e = 0; e < NE; e++) {
            gemm_q<2, false, true, false><<<dim3(48, 8), 256>>>(
                ctxb, DIM, e1 + (long)e * DFF * DIM, abss + 19 + e, 1.f / ((float)DFF * DIM),
                hmidb, DFF, LSEQ, DFF, DIM, nullptr, tsb + e * LSEQ, cntb + e);
            gemm_q<0, false, false, true><<<dim3(12, 8), 256>>>(
                hmidb, DFF, e2 + (long)e * DIM * DFF, abss + 27 + e, 1.f / ((float)DIM * DFF),
                eob, DIM, LSEQ, DIM, DFF, nullptr, tsb + e * LSEQ, cntb + e);
        }
        combine_kernel<<<LSEQ, 256>>>(eob, curb, cnw, hardb);
    }

    // ---- final select + LM head (128x128x16 double-buffered GEMM) ----
    select_kernel<<<(LSEQ * DIM + 1023) / 1024, 1024>>>(xb, curb, scal, selb);
    gemm_q_big<<<dim3((VOCAB + 127) / 128, (LSEQ + 127) / 128), 256>>>(
        selb, DIM, hw, abss + 35, 1.f / ((float)VOCAB * DIM),
        out, VOCAB, LSEQ, VOCAB, DIM);

    // ---- complexity output (tuple tail), if the buffer includes it ----
    if (out_size >= LSEQ * VOCAB + LSEQ) {
        cudaMemcpyAsync(out + (size_t)LSEQ * VOCAB, cxb, LSEQ * sizeof(float),
                        cudaMemcpyDeviceToDevice);
    }
}

// round 14
// speedup vs baseline: 2.9991x; 2.9991x over previous
#include <cuda_runtime.h>
#include <cuda_bf16.h>
#include <math.h>

#define LSEQ 512
#define DIM 768
#define DFF 3072
#define NLAYERS 8
#define NE 8
#define NSTEPS 2
#define VOCAB 50257
#define RHID 384
#define KSZ 4

// ---------------- device scratch (no cudaMalloc allowed) ----------------
__device__ double g_abssum[40];
__device__ float  g_scal[4];
__device__ float  g_x[LSEQ * DIM];
__device__ float  g_h[LSEQ * DIM];
__device__ float  g_proj[LSEQ * 2 * DIM];
__device__ float  g_mix[LSEQ * DIM];
__device__ float  g_rh[LSEQ * RHID];
__device__ float  g_cx[LSEQ];
__device__ float  g_hard[LSEQ];
__device__ float  g_cur[LSEQ * DIM];
__device__ float  g_ctxb[LSEQ * DIM];
__device__ float  g_glog[LSEQ * NE];
__device__ int    g_cnt[NE];
__device__ int    g_tokslot[NE * LSEQ];
__device__ float  g_hmid[(long)NE * LSEQ * DFF];   // per-expert slabs (parallel experts)
__device__ float  g_eo[2 * LSEQ * DIM];
__device__ float  g_selin[LSEQ * DIM];

// ---------------- helpers ----------------
__device__ __forceinline__ float blockReduceSum(float v) {
    __shared__ float sh[32];
    int lane = threadIdx.x & 31, wid = threadIdx.x >> 5;
#pragma unroll
    for (int o = 16; o; o >>= 1) v += __shfl_down_sync(0xffffffffu, v, o);
    if (lane == 0) sh[wid] = v;
    __syncthreads();
    int nw = (blockDim.x + 31) >> 5;
    v = (threadIdx.x < nw) ? sh[threadIdx.x] : 0.f;
    if (wid == 0) {
#pragma unroll
        for (int o = 16; o; o >>= 1) v += __shfl_down_sync(0xffffffffu, v, o);
    }
    return v;  // valid on thread 0
}

__device__ __forceinline__ unsigned smaddr(const void* p) {
    return (unsigned)__cvta_generic_to_shared(p);
}
__device__ __forceinline__ void ldm_x4(unsigned* r, unsigned addr) {
    asm volatile("ldmatrix.sync.aligned.m8n8.x4.shared.b16 {%0,%1,%2,%3}, [%4];"
        : "=r"(r[0]), "=r"(r[1]), "=r"(r[2]), "=r"(r[3]) : "r"(addr));
}
__device__ __forceinline__ void ldm_x2(unsigned* r, unsigned addr) {
    asm volatile("ldmatrix.sync.aligned.m8n8.x2.shared.b16 {%0,%1}, [%2];"
        : "=r"(r[0]), "=r"(r[1]) : "r"(addr));
}
__device__ __forceinline__ void mma_bf16(float* d, const unsigned* a, const unsigned* b) {
    asm volatile("mma.sync.aligned.m16n8k16.row.col.f32.bf16.bf16.f32 "
        "{%0,%1,%2,%3}, {%4,%5,%6,%7}, {%8,%9}, {%0,%1,%2,%3};"
        : "+f"(d[0]), "+f"(d[1]), "+f"(d[2]), "+f"(d[3])
        : "r"(a[0]), "r"(a[1]), "r"(a[2]), "r"(a[3]), "r"(b[0]), "r"(b[1]));
}

// XOR swizzle for 64B rows (32 bf16): conflict-free ldmatrix + stores
__device__ __forceinline__ int swz(int r, int c) {
    return r * 32 + ((c ^ ((r >> 1) & 3)) << 3);   // bf16-element index
}

__device__ __forceinline__ unsigned bfpack(float x, float y) {
    __nv_bfloat162 p = __floats2bfloat162_rn(x, y);
    return reinterpret_cast<unsigned&>(p);
}
__device__ __forceinline__ void split8(const float* v, uint4& hi, uint4& lo) {
    float h[8], l[8];
#pragma unroll
    for (int i = 0; i < 8; i++) {
        h[i] = __bfloat162float(__float2bfloat16_rn(v[i]));
        l[i] = v[i] - h[i];
    }
    hi = make_uint4(bfpack(h[0], h[1]), bfpack(h[2], h[3]), bfpack(h[4], h[5]), bfpack(h[6], h[7]));
    lo = make_uint4(bfpack(l[0], l[1]), bfpack(l[2], l[3]), bfpack(l[4], l[5]), bfpack(l[6], l[7]));
}
__device__ __forceinline__ uint4 qpack8(const float* v, float inv_g) {
    float q[8];
#pragma unroll
    for (int i = 0; i < 8; i++) q[i] = fminf(fmaxf(rintf(v[i] * inv_g), -1.f), 1.f);
    return make_uint4(bfpack(q[0], q[1]), bfpack(q[2], q[3]), bfpack(q[4], q[5]), bfpack(q[6], q[7]));
}

struct LoadRegs { uint4 ahi0, alo0, ahi1, alo1, w0, w1; };

__device__ __forceinline__ LoadRegs load_chunk(
    const float* aptr, const float* wptr, bool a_ok, bool w_ok,
    int kbase, int lhalf, float inv_g) {
    float va[16], vw[16];
#pragma unroll
    for (int i = 0; i < 16; i++) { va[i] = 0.f; vw[i] = 0.f; }
    int off = kbase + lhalf * 16;
    if (a_ok) {
#pragma unroll
        for (int q = 0; q < 4; q++)
            *reinterpret_cast<float4*>(&va[q * 4]) = *reinterpret_cast<const float4*>(aptr + off + q * 4);
    }
    if (w_ok) {
#pragma unroll
        for (int q = 0; q < 4; q++)
            *reinterpret_cast<float4*>(&vw[q * 4]) = *reinterpret_cast<const float4*>(wptr + off + q * 4);
    }
    LoadRegs L;
    split8(va, L.ahi0, L.alo0);
    split8(va + 8, L.ahi1, L.alo1);
    L.w0 = qpack8(vw, inv_g);
    L.w1 = qpack8(vw + 8, inv_g);
    return L;
}

// ---------------- small kernels ----------------
__global__ void zero_kernel(double* abss, float* scal) {
    int t = threadIdx.x;
    if (t < 40) abss[t] = 0.0;
    if (t < 4) scal[t] = 0.f;
}

__global__ void absmean_kernel(const float* __restrict__ w, long per, double* __restrict__ acc) {
    const float* p = w + (long)blockIdx.y * per;
    float s = 0.f;
    long stride = (long)gridDim.x * blockDim.x;
    for (long i = (long)blockIdx.x * blockDim.x + threadIdx.x; i < per; i += stride)
        s += fabsf(p[i]);
    s = blockReduceSum(s);
    if (threadIdx.x == 0) atomicAdd(acc + blockIdx.y, (double)s);
}

__global__ void embed_kernel(const int* __restrict__ ids, const float* __restrict__ emb,
                             float* __restrict__ x) {
    int l = blockIdx.x;
    long row = ids[l];
    const float4* src = reinterpret_cast<const float4*>(emb + row * DIM);
    float4* dst = reinterpret_cast<float4*>(x + (long)l * DIM);
    for (int i = threadIdx.x; i < DIM / 4; i += blockDim.x) dst[i] = src[i];
}

__global__ void rmsnorm_kernel(const float* __restrict__ x, const float* __restrict__ w,
                               float* __restrict__ out) {
    int l = blockIdx.x;
    const float* xr = x + (long)l * DIM;
    float v0 = xr[threadIdx.x], v1 = xr[threadIdx.x + 256], v2 = xr[threadIdx.x + 512];
    float s = blockReduceSum(v0 * v0 + v1 * v1 + v2 * v2);
    __shared__ float rstd;
    if (threadIdx.x == 0) rstd = rsqrtf(s / (float)DIM + 1e-6f);
    __syncthreads();
    float r = rstd;
    float* o = out + (long)l * DIM;
    o[threadIdx.x]       = w[threadIdx.x]       * v0 * r;
    o[threadIdx.x + 256] = w[threadIdx.x + 256] * v1 * r;
    o[threadIdx.x + 512] = w[threadIdx.x + 512] * v2 * r;
}

__global__ void convmix_kernel(const float* __restrict__ proj, const float* __restrict__ cw,
                               const float* __restrict__ cb, float* __restrict__ mix) {
    int l = blockIdx.x, d = threadIdx.x;
    float acc = cb[d];
#pragma unroll
    for (int k = 0; k < KSZ; k++) {
        int src = l - (KSZ - 1) + k;
        if (src >= 0) acc += proj[(long)src * (2 * DIM) + d] * cw[d * KSZ + k];
    }
    float gz = proj[(long)l * (2 * DIM) + DIM + d];
    float gate = gz / (1.f + expf(-gz));
    mix[(long)l * DIM + d] = acc * gate;
}

__global__ void cxpost_kernel(const float* __restrict__ cx, float* __restrict__ hard,
                              float* __restrict__ scal) {
    int t = threadIdx.x;  // 512
    float v = cx[t];
    hard[t] = (v > 0.5f) ? 1.f : 0.f;
    float s = blockReduceSum(v);
    if (t == 0) scal[0] = (s * (1.f / (float)LSEQ) > 0.1f) ? 1.f : 0.f;
}

__global__ void ctx_kernel(const float* __restrict__ cur, const float* __restrict__ te,
                           float* __restrict__ ctx, int* __restrict__ cnt) {
    int l = blockIdx.x, d = threadIdx.x;
    ctx[(long)l * DIM + d] = cur[(long)l * DIM + d] + te[d];
    if (l == 0 && d < NE) cnt[d] = 0;
}

__global__ void route_kernel(const float* __restrict__ glog, int* __restrict__ cnt,
                             int* __restrict__ tokslot) {
    int t = blockIdx.x * blockDim.x + threadIdx.x;
    if (t >= LSEQ) return;
    const float* p = glog + (long)t * NE;
    int s0 = 0; float b0 = p[0];
#pragma unroll
    for (int e = 1; e < NE; e++) { float v = p[e]; if (v > b0) { b0 = v; s0 = e; } }
    int s1 = -1; float b1 = -1e30f;
#pragma unroll
    for (int e = 0; e < NE; e++) {
        if (e == s0) continue;
        float v = p[e]; if (v > b1) { b1 = v; s1 = e; }
    }
    int p0 = atomicAdd(&cnt[s0], 1);
    tokslot[s0 * LSEQ + p0] = t;              // slot 0
    int p1 = atomicAdd(&cnt[s1], 1);
    tokslot[s1 * LSEQ + p1] = t | (1 << 16);  // slot 1
}

// refined = rmsnorm(eo0+eo1+cur, cnw); cur = hard ? refined : cur
__global__ void combine_kernel(const float* __restrict__ eo, float* __restrict__ cur,
                               const float* __restrict__ cnw, const float* __restrict__ hard) {
    int l = blockIdx.x;
    float hsel = hard[l];
    float vv[3]; float local = 0.f;
#pragma unroll
    for (int c = 0; c < 3; c++) {
        int d = threadIdx.x + c * 256;
        float v = eo[(long)l * DIM + d] + eo[(long)(LSEQ + l) * DIM + d] + cur[(long)l * DIM + d];
        vv[c] = v; local += v * v;
    }
    float s = blockReduceSum(local);
    __shared__ float rstd;
    if (threadIdx.x == 0) rstd = rsqrtf(s / (float)DIM + 1e-6f);
    __syncthreads();
    float r = rstd;
#pragma unroll
    for (int c = 0; c < 3; c++) {
        int d = threadIdx.x + c * 256;
        float refined = cnw[d] * vv[c] * r;
        float old = cur[(long)l * DIM + d];
        cur[(long)l * DIM + d] = refined * hsel + old * (1.f - hsel);
    }
}

__global__ void select_kernel(const float* __restrict__ core, const float* __restrict__ cur,
                              const float* __restrict__ scal, float* __restrict__ outp) {
    int i = blockIdx.x * blockDim.x + threadIdx.x;
    if (i < LSEQ * DIM) outp[i] = (scal[0] > 0.5f) ? cur[i] : core[i];
}

// ---------------- small quantized GEMM (64x64x16 fp32, double-buffered) ----------------
// Kept for tiny GEMMs (router, gate). Semantics identical to before.
template <int ACT, bool RESID>
__global__ __launch_bounds__(256) void gemm_q(
    const float* __restrict__ A, int lda,
    const float* __restrict__ W,
    const double* __restrict__ abssum, float invNw,
    float* __restrict__ C, int ldc,
    int M, int N, int K,
    const float* __restrict__ R) {
    int bm = blockIdx.y * 64;
    if (bm >= M) return;
    int bn = blockIdx.x * 64;

    float g = fmaxf((float)(*abssum) * invNw, 1e-5f);
    float inv_g = 1.f / g;

    __shared__ float As[2][16][64];
    __shared__ float Ws[2][16][64];

    int tid = threadIdx.x;
    int tx = tid & 15, ty = tid >> 4;
    float acc[4][4] = {};

    int lm = tid >> 2;
    int lk = (tid & 3) * 4;
    int arow = bm + lm;
    bool arow_ok = arow < M;
    long aoff = (long)(arow_ok ? arow : 0) * lda;
    int wrow = bn + lm;
    bool wrow_ok = wrow < N;
    long woff = (long)(wrow_ok ? wrow : 0) * K;

    float4 av = make_float4(0.f, 0.f, 0.f, 0.f);
    float4 wv = av;
    if (arow_ok) av = *reinterpret_cast<const float4*>(A + aoff + lk);
    if (wrow_ok) wv = *reinterpret_cast<const float4*>(W + woff + lk);
    wv.x = fminf(fmaxf(rintf(wv.x * inv_g), -1.f), 1.f);
    wv.y = fminf(fmaxf(rintf(wv.y * inv_g), -1.f), 1.f);
    wv.z = fminf(fmaxf(rintf(wv.z * inv_g), -1.f), 1.f);
    wv.w = fminf(fmaxf(rintf(wv.w * inv_g), -1.f), 1.f);
    As[0][lk + 0][lm] = av.x; As[0][lk + 1][lm] = av.y;
    As[0][lk + 2][lm] = av.z; As[0][lk + 3][lm] = av.w;
    Ws[0][lk + 0][lm] = wv.x; Ws[0][lk + 1][lm] = wv.y;
    Ws[0][lk + 2][lm] = wv.z; Ws[0][lk + 3][lm] = wv.w;
    __syncthreads();

    int buf = 0;
    for (int k0 = 0; k0 < K; k0 += 16) {
        int kn = k0 + 16;
        bool more = kn < K;
        if (more) {
            av = make_float4(0.f, 0.f, 0.f, 0.f); wv = av;
            if (arow_ok) av = *reinterpret_cast<const float4*>(A + aoff + kn + lk);
            if (wrow_ok) wv = *reinterpret_cast<const float4*>(W + woff + kn + lk);
            wv.x = fminf(fmaxf(rintf(wv.x * inv_g), -1.f), 1.f);
            wv.y = fminf(fmaxf(rintf(wv.y * inv_g), -1.f), 1.f);
            wv.z = fminf(fmaxf(rintf(wv.z * inv_g), -1.f), 1.f);
            wv.w = fminf(fmaxf(rintf(wv.w * inv_g), -1.f), 1.f);
        }
#pragma unroll
        for (int kk = 0; kk < 16; kk++) {
            float4 a4 = *reinterpret_cast<const float4*>(&As[buf][kk][ty * 4]);
            float4 b4 = *reinterpret_cast<const float4*>(&Ws[buf][kk][tx * 4]);
            float avv[4] = {a4.x, a4.y, a4.z, a4.w};
            float bvv[4] = {b4.x, b4.y, b4.z, b4.w};
#pragma unroll
            for (int i = 0; i < 4; i++)
#pragma unroll
                for (int j = 0; j < 4; j++) acc[i][j] += avv[i] * bvv[j];
        }
        if (more) {
            int nb = buf ^ 1;
            As[nb][lk + 0][lm] = av.x; As[nb][lk + 1][lm] = av.y;
            As[nb][lk + 2][lm] = av.z; As[nb][lk + 3][lm] = av.w;
            Ws[nb][lk + 0][lm] = wv.x; Ws[nb][lk + 1][lm] = wv.y;
            Ws[nb][lk + 2][lm] = wv.z; Ws[nb][lk + 3][lm] = wv.w;
            __syncthreads();
            buf = nb;
        }
    }

#pragma unroll
    for (int i = 0; i < 4; i++) {
        int row = bm + ty * 4 + i;
        if (row >= M) continue;
#pragma unroll
        for (int j = 0; j < 4; j++) {
            int col = bn + tx * 4 + j;
            if (col >= N) continue;
            float v = acc[i][j] * g;
            if (ACT == 1) v = fmaxf(v, 0.f);
            else if (ACT == 3) v = 1.f / (1.f + expf(-v));
            if (RESID) v += R[(long)row * ldc + col];
            C[(long)row * ldc + col] = v;
        }
    }
}

// ---------------- tensor-core quantized GEMM (128x128xk32, bf16 hi/lo split) ----------------
// C[M,N] = act( g * (A[M,K] @ ternary(W[N,K])^T) ) (+R)
// ACT: 0 none, 2 gelu(exact). AGATH: gather A rows via tokSlot; CSCAT: scatter C rows.
// EB: expert batch via blockIdx.z (offsets A/W/C/abssum/tokSlot/cnt).
template <int ACT, bool RESID, bool AGATH, bool CSCAT, bool EB>
__global__ __launch_bounds__(256) void gemm_t(
    const float* __restrict__ A, int lda,
    const float* __restrict__ W,
    const double* __restrict__ abssum, float invNw,
    float* __restrict__ C, int ldc,
    int M, int N, int K,
    const float* __restrict__ R,
    const int* __restrict__ tokSlot,
    const int* __restrict__ cntPtr,
    long astride, long wstride, long cstride) {
    if (EB) {
        int ez = blockIdx.z;
        A += (long)ez * astride;
        W += (long)ez * wstride;
        C += (long)ez * cstride;
        abssum += ez;
        tokSlot += ez * LSEQ;
        cntPtr += ez;
    }
    if (AGATH || CSCAT) M = *cntPtr;
    int bm = blockIdx.y * 128;
    if (bm >= M) return;
    int bn = blockIdx.x * 128;

    float g = fmaxf((float)(*abssum) * invNw, 1e-5f);
    float inv_g = 1.f / g;

    // 2 buffers x (A_hi, A_lo, W) x 128 rows x 32 bf16 = 49152 B
    __shared__ __align__(16) __nv_bfloat16 sAhi[2][128 * 32];
    __shared__ __align__(16) __nv_bfloat16 sAlo[2][128 * 32];
    __shared__ __align__(16) __nv_bfloat16 sW[2][128 * 32];

    int tid = threadIdx.x;
    int lane = tid & 31, wid = tid >> 5;
    int wm = wid & 1, wn = wid >> 1;          // warp tile 64(m) x 32(n)
    int grp = lane >> 3, lan7 = lane & 7;

    // loader: row = tid>>1 (0..127), half = tid&1 -> k offset 16
    int lrow = tid >> 1;
    int lhalf = tid & 1;

    int arow = bm + lrow;
    bool a_ok = arow < M;
    const float* aptr;
    if (AGATH) {
        int tok = a_ok ? (tokSlot[arow] & 0xFFFF) : 0;
        aptr = A + (long)tok * lda;
    } else {
        aptr = A + (long)(a_ok ? arow : 0) * lda;
    }
    int wrow = bn + lrow;
    bool w_ok = wrow < N;
    const float* wptr = W + (long)(w_ok ? wrow : 0) * K;

    float acc[4][4][4];
#pragma unroll
    for (int i = 0; i < 4; i++)
#pragma unroll
        for (int j = 0; j < 4; j++)
#pragma unroll
            for (int r = 0; r < 4; r++) acc[i][j][r] = 0.f;

#define STORE_CHUNK(B, L) do { \
    int c0_ = lhalf * 2; \
    *reinterpret_cast<uint4*>(&sAhi[B][swz(lrow, c0_)])     = (L).ahi0; \
    *reinterpret_cast<uint4*>(&sAhi[B][swz(lrow, c0_ + 1)]) = (L).ahi1; \
    *reinterpret_cast<uint4*>(&sAlo[B][swz(lrow, c0_)])     = (L).alo0; \
    *reinterpret_cast<uint4*>(&sAlo[B][swz(lrow, c0_ + 1)]) = (L).alo1; \
    *reinterpret_cast<uint4*>(&sW[B][swz(lrow, c0_)])       = (L).w0; \
    *reinterpret_cast<uint4*>(&sW[B][swz(lrow, c0_ + 1)])   = (L).w1; \
} while (0)

    LoadRegs L = load_chunk(aptr, wptr, a_ok, w_ok, 0, lhalf, inv_g);
    STORE_CHUNK(0, L);
    __syncthreads();

    int buf = 0;
    for (int k0 = 0; k0 < K; k0 += 32) {
        bool more = (k0 + 32) < K;
        LoadRegs Ln;
        if (more) Ln = load_chunk(aptr, wptr, a_ok, w_ok, k0 + 32, lhalf, inv_g);

#pragma unroll
        for (int s = 0; s < 2; s++) {
            unsigned ah[4][4], al[4][4], bb[4][2];
#pragma unroll
            for (int mi = 0; mi < 4; mi++) {
                int r = wm * 64 + mi * 16 + lan7 + ((grp & 1) << 3);
                int c = 2 * s + (grp >> 1);
                ldm_x4(ah[mi], smaddr(&sAhi[buf][swz(r, c)]));
                ldm_x4(al[mi], smaddr(&sAlo[buf][swz(r, c)]));
            }
#pragma unroll
            for (int ni = 0; ni < 4; ni++) {
                int r = wn * 32 + ni * 8 + lan7;
                int c = 2 * s + ((lane >> 3) & 1);
                ldm_x2(bb[ni], smaddr(&sW[buf][swz(r, c)]));
            }
#pragma unroll
            for (int mi = 0; mi < 4; mi++)
#pragma unroll
                for (int ni = 0; ni < 4; ni++) {
                    mma_bf16(acc[mi][ni], ah[mi], bb[ni]);
                    mma_bf16(acc[mi][ni], al[mi], bb[ni]);
                }
        }

        if (more) {
            int nb = buf ^ 1;
            STORE_CHUNK(nb, Ln);
            __syncthreads();
            buf = nb;
        }
    }
#undef STORE_CHUNK

    // epilogue: d0,d1 -> (m=lane/4, n=2*(lane%4)+{0,1}); d2,d3 -> m+8
#pragma unroll
    for (int mi = 0; mi < 4; mi++) {
#pragma unroll
        for (int half = 0; half < 2; half++) {
            int row = bm + wm * 64 + mi * 16 + (lane >> 2) + half * 8;
            if (row >= M) continue;
            long crowoff;
            if (CSCAT) {
                int ts = tokSlot[row];
                crowoff = ((long)(ts >> 16) * LSEQ + (ts & 0xFFFF)) * DIM;
            } else {
                crowoff = (long)row * ldc;
            }
#pragma unroll
            for (int ni = 0; ni < 4; ni++) {
                int col = bn + wn * 32 + ni * 8 + (lane & 3) * 2;
#pragma unroll
                for (int b = 0; b < 2; b++) {
                    int cc = col + b;
                    if (cc >= N) continue;
                    float v = acc[mi][ni][half * 2 + b] * g;
                    if (ACT == 2) v = 0.5f * v * (1.f + erff(v * 0.70710678118654752f));
                    if (RESID) v += R[(long)row * ldc + cc];
                    C[crowoff + cc] = v;
                }
            }
        }
    }
}

// ---------------- host ----------------
extern "C" void kernel_launch(void* const* d_in, const int* in_sizes, int n_in,
                              void* d_out, int out_size) {
    const int*   ids    = (const int*)d_in[0];
    const float* emb    = (const float*)d_in[1];
    const float* norm_w = (const float*)d_in[2];
    const float* in_w   = (const float*)d_in[3];
    const float* conv_w = (const float*)d_in[4];
    const float* conv_b = (const float*)d_in[5];
    const float* out_w  = (const float*)d_in[6];
    const float* rw1    = (const float*)d_in[7];
    const float* rw2    = (const float*)d_in[8];
    const float* gw     = (const float*)d_in[9];
    const float* te     = (const float*)d_in[10];
    const float* e1     = (const float*)d_in[11];
    const float* e2     = (const float*)d_in[12];
    const float* cnw    = (const float*)d_in[13];
    const float* hw     = (const float*)d_in[14];
    float* out = (float*)d_out;

    double *abss;
    float *xb, *hb, *projb, *mixb, *rhb, *cxb, *hardb, *curb, *ctxb, *glogb, *hmidb, *eob, *selb, *scal;
    int *cntb, *tsb;
    cudaGetSymbolAddress((void**)&abss,  g_abssum);
    cudaGetSymbolAddress((void**)&scal,  g_scal);
    cudaGetSymbolAddress((void**)&xb,    g_x);
    cudaGetSymbolAddress((void**)&hb,    g_h);
    cudaGetSymbolAddress((void**)&projb, g_proj);
    cudaGetSymbolAddress((void**)&mixb,  g_mix);
    cudaGetSymbolAddress((void**)&rhb,   g_rh);
    cudaGetSymbolAddress((void**)&cxb,   g_cx);
    cudaGetSymbolAddress((void**)&hardb, g_hard);
    cudaGetSymbolAddress((void**)&curb,  g_cur);
    cudaGetSymbolAddress((void**)&ctxb,  g_ctxb);
    cudaGetSymbolAddress((void**)&glogb, g_glog);
    cudaGetSymbolAddress((void**)&cntb,  g_cnt);
    cudaGetSymbolAddress((void**)&tsb,   g_tokslot);
    cudaGetSymbolAddress((void**)&hmidb, g_hmid);
    cudaGetSymbolAddress((void**)&eob,   g_eo);
    cudaGetSymbolAddress((void**)&selb,  g_selin);

    // ---- per-tensor absmean scales ----
    zero_kernel<<<1, 64>>>(abss, scal);
    absmean_kernel<<<dim3(256, NLAYERS), 256>>>(in_w,  (long)2 * DIM * DIM, abss + 0);
    absmean_kernel<<<dim3(128, NLAYERS), 256>>>(out_w, (long)DIM * DIM,     abss + 8);
    absmean_kernel<<<dim3(64, 1),  256>>>(rw1, (long)RHID * DIM, abss + 16);
    absmean_kernel<<<dim3(1, 1),   256>>>(rw2, (long)RHID,       abss + 17);
    absmean_kernel<<<dim3(4, 1),   256>>>(gw,  (long)NE * DIM,   abss + 18);
    absmean_kernel<<<dim3(256, NE), 256>>>(e1, (long)DFF * DIM,  abss + 19);
    absmean_kernel<<<dim3(256, NE), 256>>>(e2, (long)DFF * DIM,  abss + 27);
    absmean_kernel<<<dim3(512, 1), 256>>>(hw,  (long)VOCAB * DIM, abss + 35);

    // ---- embedding ----
    embed_kernel<<<LSEQ, 192>>>(ids, emb, xb);

    // ---- Mamba-style layers ----
    for (int i = 0; i < NLAYERS; i++) {
        rmsnorm_kernel<<<LSEQ, 256>>>(xb, norm_w + (long)i * DIM, hb);
        gemm_t<0, false, false, false, false><<<dim3(12, 4), 256>>>(
            hb, DIM, in_w + (long)i * 2 * DIM * DIM, abss + i, 1.f / (2.f * DIM * DIM),
            projb, 2 * DIM, LSEQ, 2 * DIM, DIM, nullptr, nullptr, nullptr, 0, 0, 0);
        convmix_kernel<<<LSEQ, DIM>>>(projb, conv_w + (long)i * DIM * KSZ,
                                      conv_b + (long)i * DIM, mixb);
        gemm_t<0, true, false, false, false><<<dim3(6, 4), 256>>>(
            mixb, DIM, out_w + (long)i * DIM * DIM, abss + 8 + i, 1.f / ((float)DIM * DIM),
            xb, DIM, LSEQ, DIM, DIM, xb, nullptr, nullptr, 0, 0, 0);
    }
    // xb now holds `core`

    // ---- ComplexityRouter ----
    gemm_q<1, false><<<dim3(6, 8), 256>>>(
        xb, DIM, rw1, abss + 16, 1.f / ((float)RHID * DIM),
        rhb, RHID, LSEQ, RHID, DIM, nullptr);
    gemm_q<3, false><<<dim3(1, 8), 256>>>(
        rhb, RHID, rw2, abss + 17, 1.f / (float)RHID,
        cxb, 1, LSEQ, 1, RHID, nullptr);
    cxpost_kernel<<<1, 512>>>(cxb, hardb, scal);

    // ---- DiffusionCouncil ----
    cudaMemcpyAsync(curb, xb, (size_t)LSEQ * DIM * sizeof(float), cudaMemcpyDeviceToDevice);
    for (int t = 0; t < NSTEPS; t++) {
        ctx_kernel<<<LSEQ, DIM>>>(curb, te + (long)t * DIM, ctxb, cntb);
        gemm_q<0, false><<<dim3(1, 8), 256>>>(
            ctxb, DIM, gw, abss + 18, 1.f / ((float)NE * DIM),
            glogb, NE, LSEQ, NE, DIM, nullptr);
        route_kernel<<<2, 256>>>(glogb, cntb, tsb);
        // all experts in one launch (blockIdx.z = expert)
        gemm_t<2, false, true, false, true><<<dim3(24, 4, NE), 256>>>(
            ctxb, DIM, e1, abss + 19, 1.f / ((float)DFF * DIM),
            hmidb, DFF, LSEQ, DFF, DIM, nullptr, tsb, cntb,
            0L, (long)DFF * DIM, (long)LSEQ * DFF);
        gemm_t<0, false, false, true, true><<<dim3(6, 4, NE), 256>>>(
            hmidb, DFF, e2, abss + 27, 1.f / ((float)DIM * DFF),
            eob, DIM, LSEQ, DIM, DFF, nullptr, tsb, cntb,
            (long)LSEQ * DFF, (long)DIM * DFF, 0L);
        combine_kernel<<<LSEQ, 256>>>(eob, curb, cnw, hardb);
    }

    // ---- final select + LM head ----
    select_kernel<<<(LSEQ * DIM + 1023) / 1024, 1024>>>(xb, curb, scal, selb);
    gemm_t<0, false, false, false, false><<<dim3((VOCAB + 127) / 128, 4), 256>>>(
        selb, DIM, hw, abss + 35, 1.f / ((float)VOCAB * DIM),
        out, VOCAB, LSEQ, VOCAB, DIM, nullptr, nullptr, nullptr, 0, 0, 0);

    // ---- complexity output (tuple tail), if the buffer includes it ----
    if (out_size >= LSEQ * VOCAB + LSEQ) {
        cudaMemcpyAsync(out + (size_t)LSEQ * VOCAB, cxb, LSEQ * sizeof(float),
                        cudaMemcpyDeviceToDevice);
    }
}